// round 2
// baseline (speedup 1.0000x reference)
#include <cuda_runtime.h>
#include <cuda_bf16.h>

// Problem constants
#define BB 2
#define NN 2048
#define EE 2048
#define HH 16
#define DD 128
#define MTOT (BB * NN)          // 4096 rows for projections
#define SCALE 0.08838834764831843f   // D^-0.5

// Scratch (allocation-free rule: __device__ globals)
// g_q, g_k: [B, H, D, N]  (transposed per-head layout for conflict-free flash loads)
// g_v:      [B, H, N, D]
// g_attn:   [B, N, E]
__device__ float g_q[(size_t)BB * HH * DD * NN];
__device__ float g_k[(size_t)BB * HH * DD * NN];
__device__ float g_v[(size_t)BB * HH * NN * DD];
__device__ float g_attn[(size_t)BB * NN * EE];

// ---------------------------------------------------------------------------
// SGEMM: C[m,e] = sum_k A[m,k] * W[e,k]   (A row-major [M,K], W row-major [Ncols,K])
// 128x128 block tile, BK=8, 256 threads, 8x8 micro-tile per thread.
// MODE 0: plain row-major store to Cout [M, Ncols]
// MODE 1: q-projection store to g_q in [B,H,D,N] layout
// MODE 2: kv-projection: e <  E -> g_k [B,H,D,N];  e >= E -> g_v [B,H,N,D]
// ---------------------------------------------------------------------------
template <int MODE>
__global__ __launch_bounds__(256) void sgemm_kernel(
    const float* __restrict__ A, const float* __restrict__ W,
    float* __restrict__ Cout, int M, int Ncols, int Kdim)
{
    __shared__ float As[8][128];
    __shared__ float Bs[8][128];

    const int tid = threadIdx.x;
    const int tx = tid & 15;        // 0..15  -> n micro
    const int ty = tid >> 4;        // 0..15  -> m micro
    const int m0 = blockIdx.y * 128;
    const int n0 = blockIdx.x * 128;

    const int ldRow = tid >> 1;            // 0..127
    const int ldK4  = (tid & 1) << 2;      // 0 or 4

    const float* Aptr = A + (size_t)(m0 + ldRow) * Kdim + ldK4;
    const float* Wptr = W + (size_t)(n0 + ldRow) * Kdim + ldK4;

    float acc[8][8];
#pragma unroll
    for (int i = 0; i < 8; ++i)
#pragma unroll
        for (int j = 0; j < 8; ++j) acc[i][j] = 0.0f;

    const int kTiles = Kdim >> 3;
    for (int kt = 0; kt < kTiles; ++kt) {
        float4 a4 = *(const float4*)(Aptr);
        float4 b4 = *(const float4*)(Wptr);
        Aptr += 8;
        Wptr += 8;

        __syncthreads();
        As[ldK4 + 0][ldRow] = a4.x;
        As[ldK4 + 1][ldRow] = a4.y;
        As[ldK4 + 2][ldRow] = a4.z;
        As[ldK4 + 3][ldRow] = a4.w;
        Bs[ldK4 + 0][ldRow] = b4.x;
        Bs[ldK4 + 1][ldRow] = b4.y;
        Bs[ldK4 + 2][ldRow] = b4.z;
        Bs[ldK4 + 3][ldRow] = b4.w;
        __syncthreads();

#pragma unroll
        for (int k = 0; k < 8; ++k) {
            float a[8], b[8];
            *(float4*)(&a[0]) = *(const float4*)(&As[k][ty * 8]);
            *(float4*)(&a[4]) = *(const float4*)(&As[k][ty * 8 + 4]);
            *(float4*)(&b[0]) = *(const float4*)(&Bs[k][tx * 8]);
            *(float4*)(&b[4]) = *(const float4*)(&Bs[k][tx * 8 + 4]);
#pragma unroll
            for (int i = 0; i < 8; ++i)
#pragma unroll
                for (int j = 0; j < 8; ++j) acc[i][j] += a[i] * b[j];
        }
    }

    // Epilogue
#pragma unroll
    for (int i = 0; i < 8; ++i) {
        const int m = m0 + ty * 8 + i;
#pragma unroll
        for (int j = 0; j < 8; ++j) {
            const int e = n0 + tx * 8 + j;
            const float v = acc[i][j];
            if (MODE == 0) {
                Cout[(size_t)m * Ncols + e] = v;
            } else if (MODE == 1) {
                const int b = m >> 11, n = m & (NN - 1);
                const int h = e >> 7, d = e & (DD - 1);
                g_q[(((size_t)(b * HH + h)) * DD + d) * NN + n] = v;
            } else {  // MODE 2
                const int b = m >> 11, n = m & (NN - 1);
                if (e < EE) {
                    const int h = e >> 7, d = e & (DD - 1);
                    g_k[(((size_t)(b * HH + h)) * DD + d) * NN + n] = v;
                } else {
                    const int e2 = e - EE;
                    const int h = e2 >> 7, d = e2 & (DD - 1);
                    g_v[(((size_t)(b * HH + h)) * NN + n) * DD + d] = v;
                }
            }
        }
    }
}

// ---------------------------------------------------------------------------
// Causal flash attention, fp32. Br = Bc = 64, D = 128.
// grid = (N/64, B*H), 256 threads.
// Q,K in [B,H,D,N]; V in [B,H,N,D]; output to g_attn [B,N,E].
// ---------------------------------------------------------------------------
#define FLASH_SMEM_FLOATS (128 * 64 + 128 * 64 + 64 * 128 + 64 * 65 + 3 * 64)
#define FLASH_SMEM_BYTES (FLASH_SMEM_FLOATS * 4)

__global__ __launch_bounds__(256) void flash_kernel()
{
    extern __shared__ float sm[];
    float* Qt   = sm;                 // [128][64]  Qt[d][r]
    float* Kt   = Qt + 128 * 64;      // [128][64]  Kt[d][c]
    float* Vs   = Kt + 128 * 64;      // [64][128]  Vs[c][d]
    float* Ss   = Vs + 64 * 128;      // [64][65]
    float* mrow = Ss + 64 * 65;       // [64]
    float* lrow = mrow + 64;          // [64]
    float* arow = lrow + 64;          // [64]

    const int tid = threadIdx.x;
    const int tx = tid & 15;          // col micro
    const int ty = tid >> 4;          // row micro
    const int bh = blockIdx.y;
    const int b  = bh >> 4;           // /HH
    const int h  = bh & (HH - 1);
    const int qi = (gridDim.x - 1) - blockIdx.x;   // long tiles first
    const int i0 = qi * 64;

    const float* Qg = g_q + (size_t)bh * DD * NN;  // [D][N]
    const float* Kg = g_k + (size_t)bh * DD * NN;  // [D][N]
    const float* Vg = g_v + (size_t)bh * NN * DD;  // [N][D]

    // Load Q tile (transposed layout: contiguous along n)
#pragma unroll
    for (int it = 0; it < 8; ++it) {
        const int f = it * 256 + tid;      // float4 index, 2048 total
        const int d = f >> 4;
        const int r4 = (f & 15) << 2;
        *(float4*)(Qt + d * 64 + r4) =
            *(const float4*)(Qg + (size_t)d * NN + i0 + r4);
    }
    if (tid < 64) { mrow[tid] = -1e30f; lrow[tid] = 0.0f; }

    float Oacc[4][8];
#pragma unroll
    for (int r = 0; r < 4; ++r)
#pragma unroll
        for (int d = 0; d < 8; ++d) Oacc[r][d] = 0.0f;

    const int jTiles = qi + 1;
    for (int jt = 0; jt < jTiles; ++jt) {
        const int j0 = jt * 64;
        __syncthreads();  // previous PV done (and Q load / init visible on iter 0)

        // Load K tile (transposed) and V tile
#pragma unroll
        for (int it = 0; it < 8; ++it) {
            const int f = it * 256 + tid;
            const int d = f >> 4;
            const int r4 = (f & 15) << 2;
            *(float4*)(Kt + d * 64 + r4) =
                *(const float4*)(Kg + (size_t)d * NN + j0 + r4);
        }
#pragma unroll
        for (int it = 0; it < 8; ++it) {
            const int f = it * 256 + tid;
            const int c = f >> 5;
            const int d4 = (f & 31) << 2;
            *(float4*)(Vs + c * 128 + d4) =
                *(const float4*)(Vg + (size_t)(j0 + c) * DD + d4);
        }
        __syncthreads();

        // S = scale * Q K^T  (4x4 per thread)
        float s[4][4];
#pragma unroll
        for (int r = 0; r < 4; ++r)
#pragma unroll
            for (int c = 0; c < 4; ++c) s[r][c] = 0.0f;

#pragma unroll 4
        for (int k = 0; k < 128; ++k) {
            float4 q4 = *(const float4*)(Qt + k * 64 + (ty << 2));
            float4 c4 = *(const float4*)(Kt + k * 64 + (tx << 2));
            const float qr[4] = {q4.x, q4.y, q4.z, q4.w};
            const float kc[4] = {c4.x, c4.y, c4.z, c4.w};
#pragma unroll
            for (int r = 0; r < 4; ++r)
#pragma unroll
                for (int c = 0; c < 4; ++c) s[r][c] += qr[r] * kc[c];
        }

        // mask + scale + store to smem
#pragma unroll
        for (int r = 0; r < 4; ++r) {
            const int i = i0 + ty * 4 + r;
#pragma unroll
            for (int c = 0; c < 4; ++c) {
                const int j = j0 + tx * 4 + c;
                float v = s[r][c] * SCALE;
                if (j > i) v = -1e30f;
                Ss[(ty * 4 + r) * 65 + tx * 4 + c] = v;
            }
        }
        __syncthreads();

        // Online softmax: one thread per row
        if (tid < 64) {
            const int r = tid;
            const float mOld = mrow[r];
            float mNew = mOld;
#pragma unroll 8
            for (int c = 0; c < 64; ++c) mNew = fmaxf(mNew, Ss[r * 65 + c]);
            const float a = __expf(mOld - mNew);
            float sum = 0.0f;
#pragma unroll 8
            for (int c = 0; c < 64; ++c) {
                const float p = __expf(Ss[r * 65 + c] - mNew);
                Ss[r * 65 + c] = p;
                sum += p;
            }
            mrow[r] = mNew;
            lrow[r] = lrow[r] * a + sum;
            arow[r] = a;
        }
        __syncthreads();

        // Rescale O and accumulate P @ V  (4 rows x 8 d-cols per thread)
#pragma unroll
        for (int r = 0; r < 4; ++r) {
            const float a = arow[ty * 4 + r];
#pragma unroll
            for (int d = 0; d < 8; ++d) Oacc[r][d] *= a;
        }
#pragma unroll 2
        for (int c = 0; c < 64; ++c) {
            float4 v0 = *(const float4*)(Vs + c * 128 + (tx << 3));
            float4 v1 = *(const float4*)(Vs + c * 128 + (tx << 3) + 4);
            const float vv[8] = {v0.x, v0.y, v0.z, v0.w, v1.x, v1.y, v1.z, v1.w};
#pragma unroll
            for (int r = 0; r < 4; ++r) {
                const float p = Ss[(ty * 4 + r) * 65 + c];
#pragma unroll
                for (int d = 0; d < 8; ++d) Oacc[r][d] += p * vv[d];
            }
        }
    }

    // Final normalize + store to g_attn [B,N,E]
#pragma unroll
    for (int r = 0; r < 4; ++r) {
        const int i = i0 + ty * 4 + r;
        const float inv = 1.0f / lrow[ty * 4 + r];
        float* dst = g_attn + ((size_t)(b * NN + i)) * EE + h * DD + (tx << 3);
        float4 o0, o1;
        o0.x = Oacc[r][0] * inv; o0.y = Oacc[r][1] * inv;
        o0.z = Oacc[r][2] * inv; o0.w = Oacc[r][3] * inv;
        o1.x = Oacc[r][4] * inv; o1.y = Oacc[r][5] * inv;
        o1.z = Oacc[r][6] * inv; o1.w = Oacc[r][7] * inv;
        *(float4*)(dst) = o0;
        *(float4*)(dst + 4) = o1;
    }
}

// ---------------------------------------------------------------------------
// Launch
// ---------------------------------------------------------------------------
extern "C" void kernel_launch(void* const* d_in, const int* in_sizes, int n_in,
                              void* d_out, int out_size)
{
    const float* x    = (const float*)d_in[0];
    const float* Wq   = (const float*)d_in[1];
    const float* Wkv  = (const float*)d_in[2];
    const float* Wout = (const float*)d_in[3];
    float* out = (float*)d_out;

    // Q projection -> g_q (transposed head layout)
    sgemm_kernel<1><<<dim3(EE / 128, MTOT / 128), 256>>>(x, Wq, nullptr, MTOT, EE, EE);
    // KV projection -> g_k (transposed), g_v
    sgemm_kernel<2><<<dim3(2 * EE / 128, MTOT / 128), 256>>>(x, Wkv, nullptr, MTOT, 2 * EE, EE);

    // Flash attention
    cudaFuncSetAttribute(flash_kernel, cudaFuncAttributeMaxDynamicSharedMemorySize,
                         FLASH_SMEM_BYTES);
    flash_kernel<<<dim3(NN / 64, BB * HH), 256, FLASH_SMEM_BYTES>>>();

    // Output projection: g_attn @ Wout^T -> out
    float* attn_ptr = nullptr;
    cudaGetSymbolAddress((void**)&attn_ptr, g_attn);
    sgemm_kernel<0><<<dim3(EE / 128, MTOT / 128), 256>>>(attn_ptr, Wout, out, MTOT, EE, EE);
}

// round 6
// speedup vs baseline: 1.8218x; 1.8218x over previous
#include <cuda_runtime.h>
#include <cuda_bf16.h>
#include <cstdint>

// Problem constants
#define BB 2
#define NN 2048
#define EE 2048
#define HH 16
#define DD 128
#define MTOT (BB * NN)
#define SCALE 0.08838834764831843f

// ---------------------------------------------------------------------------
// Device scratch (allocation-free rule)
// ---------------------------------------------------------------------------
__device__ float g_q[(size_t)BB * HH * DD * NN];   // [B,H,D,N]
__device__ float g_k[(size_t)BB * HH * DD * NN];   // [B,H,D,N]
__device__ float g_v[(size_t)BB * HH * NN * DD];   // [B,H,N,D]

__device__ __nv_bfloat16 s_xh[8388608],  s_xl[8388608];   // x split     [M,K]
__device__ __nv_bfloat16 s_wqh[4194304], s_wql[4194304];  // Wq split    [E,K]
__device__ __nv_bfloat16 s_wkh[8388608], s_wkl[8388608];  // Wkv split   [2E,K]
__device__ __nv_bfloat16 s_woh[4194304], s_wol[4194304];  // Wout split  [E,K]
__device__ __nv_bfloat16 s_ah[8388608],  s_al[8388608];   // attn out split [B,N,E]

// ---------------------------------------------------------------------------
// Helpers
// ---------------------------------------------------------------------------
__device__ __forceinline__ uint32_t smem_u32(const void* p) {
    uint32_t a;
    asm("{ .reg .u64 t; cvta.to.shared.u64 t, %1; cvt.u32.u64 %0, t; }"
        : "=r"(a) : "l"(p));
    return a;
}
__device__ __forceinline__ void cp16(uint32_t dst, const void* src) {
    asm volatile("cp.async.cg.shared.global [%0], [%1], 16;"
                 :: "r"(dst), "l"(src));
}
__device__ __forceinline__ void cp_commit() {
    asm volatile("cp.async.commit_group;");
}
// SW64 swizzle for 64-byte rows: XOR byte bits [5:4] with bits [8:7]
__device__ __forceinline__ uint32_t swz(uint32_t off) {
    return off ^ ((off >> 3) & 0x30);
}
__device__ __forceinline__ void ldmx4(uint32_t* f, uint32_t addr) {
    asm volatile("ldmatrix.sync.aligned.m8n8.x4.shared.b16 {%0,%1,%2,%3}, [%4];"
                 : "=r"(f[0]), "=r"(f[1]), "=r"(f[2]), "=r"(f[3]) : "r"(addr));
}
__device__ __forceinline__ void mma16816(float* c, const uint32_t* a,
                                         uint32_t b0, uint32_t b1) {
    asm volatile(
        "mma.sync.aligned.m16n8k16.row.col.f32.bf16.bf16.f32 "
        "{%0,%1,%2,%3}, {%4,%5,%6,%7}, {%8,%9}, {%0,%1,%2,%3};"
        : "+f"(c[0]), "+f"(c[1]), "+f"(c[2]), "+f"(c[3])
        : "r"(a[0]), "r"(a[1]), "r"(a[2]), "r"(a[3]), "r"(b0), "r"(b1));
}

// ---------------------------------------------------------------------------
// Split kernel: fp32 -> (hi, lo) bf16
// ---------------------------------------------------------------------------
__global__ __launch_bounds__(256) void split_kernel(
    const float* __restrict__ src, __nv_bfloat16* __restrict__ hi,
    __nv_bfloat16* __restrict__ lo, int n4)
{
    int i = blockIdx.x * blockDim.x + threadIdx.x;
    if (i >= n4) return;
    float4 v = ((const float4*)src)[i];
    float vv[4] = {v.x, v.y, v.z, v.w};
    __nv_bfloat16 h[4], l[4];
#pragma unroll
    for (int j = 0; j < 4; ++j) {
        h[j] = __float2bfloat16(vv[j]);
        l[j] = __float2bfloat16(vv[j] - __bfloat162float(h[j]));
    }
    ((uint2*)hi)[i] = *(const uint2*)h;
    ((uint2*)lo)[i] = *(const uint2*)l;
}

// ---------------------------------------------------------------------------
// bf16-split GEMM via mma.sync: C = A @ W^T
// 128x128 CTA tile, K-chunk 32 bf16, double-buffered cp.async, 8 warps (2x4).
// Per-warp: 64x32 (4 m-tiles of 16 x 4 n-tiles of 8), 3-term split.
// MODE 0: Cout [M,E]   MODE 1: g_q [B,H,D,N]   MODE 2: g_k / g_v
// ---------------------------------------------------------------------------
#define TILE_BYTES 8192            // 128 rows x 64 bytes (32 bf16)
#define STAGE_BYTES (4 * TILE_BYTES)
#define GEMM_SMEM 67584            // max(2 stages = 64KB, epilogue 128*132*4)

__device__ __forceinline__ void load_chunk(
    uint32_t stage, const __nv_bfloat16* Ahp, const __nv_bfloat16* Alp,
    const __nv_bfloat16* Whp, const __nv_bfloat16* Wlp,
    int m0, int n0, int k0, int Kdim, int tid)
{
#pragma unroll
    for (int t = 0; t < 2; ++t) {
        const int c = tid + t * 256;           // 0..511 : 16B chunk index
        const int row = c >> 2;
        const int kc = c & 3;
        const uint32_t so = swz((uint32_t)(row * 64 + kc * 16));
        const size_t gA = (size_t)(m0 + row) * Kdim + k0 + kc * 8;
        const size_t gW = (size_t)(n0 + row) * Kdim + k0 + kc * 8;
        cp16(stage + 0 * TILE_BYTES + so, Ahp + gA);
        cp16(stage + 1 * TILE_BYTES + so, Alp + gA);
        cp16(stage + 2 * TILE_BYTES + so, Whp + gW);
        cp16(stage + 3 * TILE_BYTES + so, Wlp + gW);
    }
}

template <int MODE>
__global__ void __launch_bounds__(256) gemm_mma(
    const __nv_bfloat16* __restrict__ Ahp, const __nv_bfloat16* __restrict__ Alp,
    const __nv_bfloat16* __restrict__ Whp, const __nv_bfloat16* __restrict__ Wlp,
    float* __restrict__ Cout, int Kdim)
{
    extern __shared__ char smem[];
    const uint32_t sb = smem_u32(smem);
    const int tid = threadIdx.x;
    const int lane = tid & 31;
    const int w = tid >> 5;
    const int wm = w >> 2;          // 0..1 -> 64 rows each
    const int wn = w & 3;           // 0..3 -> 32 cols each
    const int m0 = blockIdx.y * 128;
    const int n0 = blockIdx.x * 128;

    float acc[4][4][4];
#pragma unroll
    for (int i = 0; i < 4; ++i)
#pragma unroll
        for (int j = 0; j < 4; ++j)
#pragma unroll
            for (int r = 0; r < 4; ++r) acc[i][j][r] = 0.0f;

    // ldmatrix lane-address components (within a tile)
    const int sel = lane >> 3;                 // matrix select 0..3
    const int lrow8 = ((sel & 1) << 3) + (lane & 7);
    const int lkc = sel >> 1;                  // 0/1 : 16B chunk within k16

    const int nk = Kdim >> 5;                  // 64 chunks

    // Prologue
    load_chunk(sb, Ahp, Alp, Whp, Wlp, m0, n0, 0, Kdim, tid);
    cp_commit();

    for (int kt = 0; kt < nk; ++kt) {
        const int buf = kt & 1;
        const uint32_t stage = sb + buf * STAGE_BYTES;

        if (kt + 1 < nk) {
            load_chunk(sb + (buf ^ 1) * STAGE_BYTES, Ahp, Alp, Whp, Wlp,
                       m0, n0, (kt + 1) << 5, Kdim, tid);
            cp_commit();
            asm volatile("cp.async.wait_group 1;");
        } else {
            asm volatile("cp.async.wait_group 0;");
        }
        __syncthreads();

#pragma unroll
        for (int kk = 0; kk < 2; ++kk) {
            const int kchunk = kk * 2 + lkc;
            // A fragments (hi, lo): 4 m-tiles each
            uint32_t ah[4][4], al[4][4];
#pragma unroll
            for (int i = 0; i < 4; ++i) {
                const int r = wm * 64 + i * 16 + lrow8;
                const uint32_t off = swz((uint32_t)(r * 64 + kchunk * 16));
                ldmx4(ah[i], stage + 0 * TILE_BYTES + off);
                ldmx4(al[i], stage + 1 * TILE_BYTES + off);
            }
            // B fragments (hi, lo): 2 ldmatrix.x4 cover 4 n8-tiles
            uint32_t bh[2][4], bl[2][4];
#pragma unroll
            for (int j2 = 0; j2 < 2; ++j2) {
                const int r = wn * 32 + j2 * 16 + lrow8;
                const uint32_t off = swz((uint32_t)(r * 64 + kchunk * 16));
                ldmx4(bh[j2], stage + 2 * TILE_BYTES + off);
                ldmx4(bl[j2], stage + 3 * TILE_BYTES + off);
            }
#pragma unroll
            for (int i = 0; i < 4; ++i) {
#pragma unroll
                for (int j = 0; j < 4; ++j) {
                    const int j2 = j >> 1, jo = j & 1;
                    // Ah*Wh + Al*Wh + Ah*Wl
                    mma16816(acc[i][j], ah[i], bh[j2][jo], bh[j2][2 + jo]);
                    mma16816(acc[i][j], al[i], bh[j2][jo], bh[j2][2 + jo]);
                    mma16816(acc[i][j], ah[i], bl[j2][jo], bl[j2][2 + jo]);
                }
            }
        }
        __syncthreads();
    }

    // ---- Epilogue: frags -> padded smem -> mode-specific global stores ----
    float* Ss = (float*)smem;   // [128][132]
#pragma unroll
    for (int i = 0; i < 4; ++i) {
        const int r = wm * 64 + i * 16 + (lane >> 2);
#pragma unroll
        for (int j = 0; j < 4; ++j) {
            const int cc = wn * 32 + j * 8 + 2 * (lane & 3);
            Ss[r * 132 + cc]           = acc[i][j][0];
            Ss[r * 132 + cc + 1]       = acc[i][j][1];
            Ss[(r + 8) * 132 + cc]     = acc[i][j][2];
            Ss[(r + 8) * 132 + cc + 1] = acc[i][j][3];
        }
    }
    __syncthreads();

    const int b = m0 >> 11;
    const int nbase = m0 & (NN - 1);

    if (MODE == 0) {
#pragma unroll
        for (int it = 0; it < 16; ++it) {
            const int f = it * 256 + tid;
            const int r = f >> 5;
            const int c4 = (f & 31) << 2;
            float4 v = *(const float4*)(Ss + r * 132 + c4);
            *(float4*)(Cout + (size_t)(m0 + r) * EE + n0 + c4) = v;
        }
    } else if (MODE == 1 || (MODE == 2 && n0 < EE)) {
        // transposed store into g_q / g_k  [B,H,D,N]
        float* dstbase = (MODE == 1) ? g_q : g_k;
        const int h = (n0 & (EE - 1)) >> 7;
        const int col = tid >> 1;
        const int rh = tid & 1;
        float* dst = dstbase + ((size_t)(b * HH + h) * DD + col) * NN + nbase + (rh << 6);
#pragma unroll
        for (int i = 0; i < 16; ++i) {
            const int r = (rh << 6) + (i << 2);
            float4 v;
            v.x = Ss[(r + 0) * 132 + col];
            v.y = Ss[(r + 1) * 132 + col];
            v.z = Ss[(r + 2) * 132 + col];
            v.w = Ss[(r + 3) * 132 + col];
            *(float4*)(dst + (i << 2)) = v;
        }
    } else {
        // MODE 2, n0 >= EE : V store [B,H,N,D]
        const int h2 = (n0 - EE) >> 7;
#pragma unroll
        for (int it = 0; it < 16; ++it) {
            const int f = it * 256 + tid;
            const int r = f >> 5;
            const int c4 = (f & 31) << 2;
            float4 v = *(const float4*)(Ss + r * 132 + c4);
            *(float4*)(g_v + ((size_t)(b * HH + h2) * NN + nbase + r) * DD + c4) = v;
        }
    }
}

// ---------------------------------------------------------------------------
// Causal flash attention, fp32. Br = Bc = 64, D = 128.
// Writes split-bf16 output directly to s_ah / s_al  [B,N,E].
// ---------------------------------------------------------------------------
#define FLASH_SMEM_FLOATS (128 * 64 + 128 * 64 + 64 * 128 + 64 * 65 + 3 * 64)
#define FLASH_SMEM_BYTES (FLASH_SMEM_FLOATS * 4)

__global__ __launch_bounds__(256) void flash_kernel()
{
    extern __shared__ float sm[];
    float* Qt   = sm;
    float* Kt   = Qt + 128 * 64;
    float* Vs   = Kt + 128 * 64;
    float* Ssm  = Vs + 64 * 128;
    float* mrow = Ssm + 64 * 65;
    float* lrow = mrow + 64;
    float* arow = lrow + 64;

    const int tid = threadIdx.x;
    const int tx = tid & 15;
    const int ty = tid >> 4;
    const int bh = blockIdx.y;
    const int b  = bh >> 4;
    const int h  = bh & (HH - 1);
    const int qi = (gridDim.x - 1) - blockIdx.x;
    const int i0 = qi * 64;

    const float* Qg = g_q + (size_t)bh * DD * NN;
    const float* Kg = g_k + (size_t)bh * DD * NN;
    const float* Vg = g_v + (size_t)bh * NN * DD;

#pragma unroll
    for (int it = 0; it < 8; ++it) {
        const int f = it * 256 + tid;
        const int d = f >> 4;
        const int r4 = (f & 15) << 2;
        *(float4*)(Qt + d * 64 + r4) = *(const float4*)(Qg + (size_t)d * NN + i0 + r4);
    }
    if (tid < 64) { mrow[tid] = -1e30f; lrow[tid] = 0.0f; }

    float Oacc[4][8];
#pragma unroll
    for (int r = 0; r < 4; ++r)
#pragma unroll
        for (int d = 0; d < 8; ++d) Oacc[r][d] = 0.0f;

    const int jTiles = qi + 1;
    for (int jt = 0; jt < jTiles; ++jt) {
        const int j0 = jt * 64;
        __syncthreads();

#pragma unroll
        for (int it = 0; it < 8; ++it) {
            const int f = it * 256 + tid;
            const int d = f >> 4;
            const int r4 = (f & 15) << 2;
            *(float4*)(Kt + d * 64 + r4) = *(const float4*)(Kg + (size_t)d * NN + j0 + r4);
        }
#pragma unroll
        for (int it = 0; it < 8; ++it) {
            const int f = it * 256 + tid;
            const int c = f >> 5;
            const int d4 = (f & 31) << 2;
            *(float4*)(Vs + c * 128 + d4) = *(const float4*)(Vg + (size_t)(j0 + c) * DD + d4);
        }
        __syncthreads();

        float s[4][4];
#pragma unroll
        for (int r = 0; r < 4; ++r)
#pragma unroll
            for (int c = 0; c < 4; ++c) s[r][c] = 0.0f;

#pragma unroll 4
        for (int k = 0; k < 128; ++k) {
            float4 q4 = *(const float4*)(Qt + k * 64 + (ty << 2));
            float4 c4 = *(const float4*)(Kt + k * 64 + (tx << 2));
            const float qr[4] = {q4.x, q4.y, q4.z, q4.w};
            const float kc[4] = {c4.x, c4.y, c4.z, c4.w};
#pragma unroll
            for (int r = 0; r < 4; ++r)
#pragma unroll
                for (int c = 0; c < 4; ++c) s[r][c] += qr[r] * kc[c];
        }

#pragma unroll
        for (int r = 0; r < 4; ++r) {
            const int i = i0 + ty * 4 + r;
#pragma unroll
            for (int c = 0; c < 4; ++c) {
                const int j = j0 + tx * 4 + c;
                float v = s[r][c] * SCALE;
                if (j > i) v = -1e30f;
                Ssm[(ty * 4 + r) * 65 + tx * 4 + c] = v;
            }
        }
        __syncthreads();

        if (tid < 64) {
            const int r = tid;
            const float mOld = mrow[r];
            float mNew = mOld;
#pragma unroll 8
            for (int c = 0; c < 64; ++c) mNew = fmaxf(mNew, Ssm[r * 65 + c]);
            const float a = __expf(mOld - mNew);
            float sum = 0.0f;
#pragma unroll 8
            for (int c = 0; c < 64; ++c) {
                const float p = __expf(Ssm[r * 65 + c] - mNew);
                Ssm[r * 65 + c] = p;
                sum += p;
            }
            mrow[r] = mNew;
            lrow[r] = lrow[r] * a + sum;
            arow[r] = a;
        }
        __syncthreads();

#pragma unroll
        for (int r = 0; r < 4; ++r) {
            const float a = arow[ty * 4 + r];
#pragma unroll
            for (int d = 0; d < 8; ++d) Oacc[r][d] *= a;
        }
#pragma unroll 2
        for (int c = 0; c < 64; ++c) {
            float4 v0 = *(const float4*)(Vs + c * 128 + (tx << 3));
            float4 v1 = *(const float4*)(Vs + c * 128 + (tx << 3) + 4);
            const float vv[8] = {v0.x, v0.y, v0.z, v0.w, v1.x, v1.y, v1.z, v1.w};
#pragma unroll
            for (int r = 0; r < 4; ++r) {
                const float p = Ssm[(ty * 4 + r) * 65 + c];
#pragma unroll
                for (int d = 0; d < 8; ++d) Oacc[r][d] += p * vv[d];
            }
        }
    }

    // Final normalize + split-bf16 store to s_ah/s_al [B,N,E]
#pragma unroll
    for (int r = 0; r < 4; ++r) {
        const int i = i0 + ty * 4 + r;
        const float inv = 1.0f / lrow[ty * 4 + r];
        const size_t idx = ((size_t)(b * NN + i)) * EE + h * DD + (tx << 3);
        __nv_bfloat16 hi8[8], lo8[8];
#pragma unroll
        for (int d = 0; d < 8; ++d) {
            const float o = Oacc[r][d] * inv;
            hi8[d] = __float2bfloat16(o);
            lo8[d] = __float2bfloat16(o - __bfloat162float(hi8[d]));
        }
        *(uint4*)(s_ah + idx) = *(const uint4*)hi8;
        *(uint4*)(s_al + idx) = *(const uint4*)lo8;
    }
}

// ---------------------------------------------------------------------------
// Launch
// ---------------------------------------------------------------------------
extern "C" void kernel_launch(void* const* d_in, const int* in_sizes, int n_in,
                              void* d_out, int out_size)
{
    const float* x    = (const float*)d_in[0];
    const float* Wq   = (const float*)d_in[1];
    const float* Wkv  = (const float*)d_in[2];
    const float* Wout = (const float*)d_in[3];
    float* out = (float*)d_out;

    void *xh, *xl, *wqh, *wql, *wkh, *wkl, *woh, *wol, *ah, *al;
    cudaGetSymbolAddress(&xh, s_xh);   cudaGetSymbolAddress(&xl, s_xl);
    cudaGetSymbolAddress(&wqh, s_wqh); cudaGetSymbolAddress(&wql, s_wql);
    cudaGetSymbolAddress(&wkh, s_wkh); cudaGetSymbolAddress(&wkl, s_wkl);
    cudaGetSymbolAddress(&woh, s_woh); cudaGetSymbolAddress(&wol, s_wol);
    cudaGetSymbolAddress(&ah, s_ah);   cudaGetSymbolAddress(&al, s_al);

    // Split fp32 inputs into bf16 hi/lo
    split_kernel<<<8192, 256>>>(x,    (__nv_bfloat16*)xh,  (__nv_bfloat16*)xl,  2097152);
    split_kernel<<<4096, 256>>>(Wq,   (__nv_bfloat16*)wqh, (__nv_bfloat16*)wql, 1048576);
    split_kernel<<<8192, 256>>>(Wkv,  (__nv_bfloat16*)wkh, (__nv_bfloat16*)wkl, 2097152);
    split_kernel<<<4096, 256>>>(Wout, (__nv_bfloat16*)wol ? (const float*)0 == 0 ? (__nv_bfloat16*)woh : (__nv_bfloat16*)woh : (__nv_bfloat16*)woh, (__nv_bfloat16*)wol, 1048576);

    cudaFuncSetAttribute(gemm_mma<0>, cudaFuncAttributeMaxDynamicSharedMemorySize, GEMM_SMEM);
    cudaFuncSetAttribute(gemm_mma<1>, cudaFuncAttributeMaxDynamicSharedMemorySize, GEMM_SMEM);
    cudaFuncSetAttribute(gemm_mma<2>, cudaFuncAttributeMaxDynamicSharedMemorySize, GEMM_SMEM);

    // Q projection -> g_q (transposed), KV projection -> g_k / g_v
    gemm_mma<1><<<dim3(EE / 128, MTOT / 128), 256, GEMM_SMEM>>>(
        (const __nv_bfloat16*)xh, (const __nv_bfloat16*)xl,
        (const __nv_bfloat16*)wqh, (const __nv_bfloat16*)wql, nullptr, EE);
    gemm_mma<2><<<dim3(2 * EE / 128, MTOT / 128), 256, GEMM_SMEM>>>(
        (const __nv_bfloat16*)xh, (const __nv_bfloat16*)xl,
        (const __nv_bfloat16*)wkh, (const __nv_bfloat16*)wkl, nullptr, EE);

    // Flash attention (fp32) -> split-bf16 s_ah/s_al
    cudaFuncSetAttribute(flash_kernel, cudaFuncAttributeMaxDynamicSharedMemorySize,
                         FLASH_SMEM_BYTES);
    flash_kernel<<<dim3(NN / 64, BB * HH), 256, FLASH_SMEM_BYTES>>>();

    // Output projection -> out
    gemm_mma<0><<<dim3(EE / 128, MTOT / 128), 256, GEMM_SMEM>>>(
        (const __nv_bfloat16*)ah, (const __nv_bfloat16*)al,
        (const __nv_bfloat16*)woh, (const __nv_bfloat16*)wol, out, EE);
}

// round 10
// speedup vs baseline: 2.8392x; 1.5584x over previous
#include <cuda_runtime.h>
#include <cuda_bf16.h>
#include <cstdint>

// Problem constants
#define BB 2
#define NN 2048
#define EE 2048
#define HH 16
#define DD 128
#define MTOT (BB * NN)
#define SCALE 0.08838834764831843f

// ---------------------------------------------------------------------------
// Device scratch (allocation-free rule)
// ---------------------------------------------------------------------------
__device__ __nv_bfloat16 g_qh[(size_t)BB * HH * NN * DD];  // Q hi [B,H,N,D]
__device__ __nv_bfloat16 g_ql[(size_t)BB * HH * NN * DD];  // Q lo
__device__ __nv_bfloat16 g_kh[(size_t)BB * HH * NN * DD];  // K hi [B,H,N,D]
__device__ __nv_bfloat16 g_kl[(size_t)BB * HH * NN * DD];  // K lo
__device__ __nv_bfloat16 g_vth[(size_t)BB * HH * DD * NN]; // V hi [B,H,D,N]
__device__ __nv_bfloat16 g_vtl[(size_t)BB * HH * DD * NN]; // V lo [B,H,D,N]

__device__ __nv_bfloat16 s_xh[8388608],  s_xl[8388608];   // x split     [M,K]
__device__ __nv_bfloat16 s_wqh[4194304], s_wql[4194304];  // Wq split    [E,K]
__device__ __nv_bfloat16 s_wkh[8388608], s_wkl[8388608];  // Wkv split   [2E,K]
__device__ __nv_bfloat16 s_woh[4194304], s_wol[4194304];  // Wout split  [E,K]
__device__ __nv_bfloat16 s_ah[8388608],  s_al[8388608];   // attn out split [B,N,E]

// ---------------------------------------------------------------------------
// Helpers
// ---------------------------------------------------------------------------
__device__ __forceinline__ uint32_t smem_u32(const void* p) {
    uint32_t a;
    asm("{ .reg .u64 t; cvta.to.shared.u64 t, %1; cvt.u32.u64 %0, t; }"
        : "=r"(a) : "l"(p));
    return a;
}
__device__ __forceinline__ void cp16(uint32_t dst, const void* src) {
    asm volatile("cp.async.cg.shared.global [%0], [%1], 16;"
                 :: "r"(dst), "l"(src));
}
__device__ __forceinline__ void cp_commit() {
    asm volatile("cp.async.commit_group;");
}
__device__ __forceinline__ uint32_t swz(uint32_t off) {   // SW64 for 64B rows
    return off ^ ((off >> 3) & 0x30);
}
__device__ __forceinline__ void ldmx4(uint32_t* f, uint32_t addr) {
    asm volatile("ldmatrix.sync.aligned.m8n8.x4.shared.b16 {%0,%1,%2,%3}, [%4];"
                 : "=r"(f[0]), "=r"(f[1]), "=r"(f[2]), "=r"(f[3]) : "r"(addr));
}
__device__ __forceinline__ void mma16816(float* c, const uint32_t* a,
                                         uint32_t b0, uint32_t b1) {
    asm volatile(
        "mma.sync.aligned.m16n8k16.row.col.f32.bf16.bf16.f32 "
        "{%0,%1,%2,%3}, {%4,%5,%6,%7}, {%8,%9}, {%0,%1,%2,%3};"
        : "+f"(c[0]), "+f"(c[1]), "+f"(c[2]), "+f"(c[3])
        : "r"(a[0]), "r"(a[1]), "r"(a[2]), "r"(a[3]), "r"(b0), "r"(b1));
}
__device__ __forceinline__ uint32_t packbf(float a, float b) {
    __nv_bfloat162 t = __floats2bfloat162_rn(a, b);
    return *(uint32_t*)&t;
}

// ---------------------------------------------------------------------------
// Split kernel: fp32 -> (hi, lo) bf16
// ---------------------------------------------------------------------------
__global__ __launch_bounds__(256) void split_kernel(
    const float* __restrict__ src, __nv_bfloat16* __restrict__ hi,
    __nv_bfloat16* __restrict__ lo, int n4)
{
    int i = blockIdx.x * blockDim.x + threadIdx.x;
    if (i >= n4) return;
    float4 v = ((const float4*)src)[i];
    float vv[4] = {v.x, v.y, v.z, v.w};
    __nv_bfloat16 h[4], l[4];
#pragma unroll
    for (int j = 0; j < 4; ++j) {
        h[j] = __float2bfloat16(vv[j]);
        l[j] = __float2bfloat16(vv[j] - __bfloat162float(h[j]));
    }
    ((uint2*)hi)[i] = *(const uint2*)h;
    ((uint2*)lo)[i] = *(const uint2*)l;
}

// ---------------------------------------------------------------------------
// bf16-split GEMM via mma.sync: C = A @ W^T
// MODE 0: Cout fp32 [M,E]
// MODE 1: Q -> g_qh/g_ql bf16 split [B,H,N,D]
// MODE 2: e<E: K -> g_kh/g_kl [B,H,N,D];  e>=E: V -> g_vth/g_vtl [B,H,D,N]
// ---------------------------------------------------------------------------
#define TILE_BYTES 8192
#define STAGE_BYTES (4 * TILE_BYTES)
#define GEMM_SMEM 67584

__device__ __forceinline__ void load_chunk(
    uint32_t stage, const __nv_bfloat16* Ahp, const __nv_bfloat16* Alp,
    const __nv_bfloat16* Whp, const __nv_bfloat16* Wlp,
    int m0, int n0, int k0, int Kdim, int tid)
{
#pragma unroll
    for (int t = 0; t < 2; ++t) {
        const int c = tid + t * 256;
        const int row = c >> 2;
        const int kc = c & 3;
        const uint32_t so = swz((uint32_t)(row * 64 + kc * 16));
        const size_t gA = (size_t)(m0 + row) * Kdim + k0 + kc * 8;
        const size_t gW = (size_t)(n0 + row) * Kdim + k0 + kc * 8;
        cp16(stage + 0 * TILE_BYTES + so, Ahp + gA);
        cp16(stage + 1 * TILE_BYTES + so, Alp + gA);
        cp16(stage + 2 * TILE_BYTES + so, Whp + gW);
        cp16(stage + 3 * TILE_BYTES + so, Wlp + gW);
    }
}

template <int MODE>
__global__ void __launch_bounds__(256) gemm_mma(
    const __nv_bfloat16* __restrict__ Ahp, const __nv_bfloat16* __restrict__ Alp,
    const __nv_bfloat16* __restrict__ Whp, const __nv_bfloat16* __restrict__ Wlp,
    float* __restrict__ Cout, int Kdim)
{
    extern __shared__ char smem[];
    const uint32_t sb = smem_u32(smem);
    const int tid = threadIdx.x;
    const int lane = tid & 31;
    const int w = tid >> 5;
    const int wm = w >> 2;
    const int wn = w & 3;
    const int m0 = blockIdx.y * 128;
    const int n0 = blockIdx.x * 128;

    float acc[4][4][4];
#pragma unroll
    for (int i = 0; i < 4; ++i)
#pragma unroll
        for (int j = 0; j < 4; ++j)
#pragma unroll
            for (int r = 0; r < 4; ++r) acc[i][j][r] = 0.0f;

    const int sel = lane >> 3;
    const int lrow8 = ((sel & 1) << 3) + (lane & 7);
    const int lkc = sel >> 1;

    const int nk = Kdim >> 5;
    load_chunk(sb, Ahp, Alp, Whp, Wlp, m0, n0, 0, Kdim, tid);
    cp_commit();

    for (int kt = 0; kt < nk; ++kt) {
        const int buf = kt & 1;
        const uint32_t stage = sb + buf * STAGE_BYTES;

        if (kt + 1 < nk) {
            load_chunk(sb + (buf ^ 1) * STAGE_BYTES, Ahp, Alp, Whp, Wlp,
                       m0, n0, (kt + 1) << 5, Kdim, tid);
            cp_commit();
            asm volatile("cp.async.wait_group 1;");
        } else {
            asm volatile("cp.async.wait_group 0;");
        }
        __syncthreads();

#pragma unroll
        for (int kk = 0; kk < 2; ++kk) {
            const int kchunk = kk * 2 + lkc;
            uint32_t ah[4][4], al[4][4];
#pragma unroll
            for (int i = 0; i < 4; ++i) {
                const int r = wm * 64 + i * 16 + lrow8;
                const uint32_t off = swz((uint32_t)(r * 64 + kchunk * 16));
                ldmx4(ah[i], stage + 0 * TILE_BYTES + off);
                ldmx4(al[i], stage + 1 * TILE_BYTES + off);
            }
            uint32_t bh[2][4], bl[2][4];
#pragma unroll
            for (int j2 = 0; j2 < 2; ++j2) {
                const int r = wn * 32 + j2 * 16 + lrow8;
                const uint32_t off = swz((uint32_t)(r * 64 + kchunk * 16));
                ldmx4(bh[j2], stage + 2 * TILE_BYTES + off);
                ldmx4(bl[j2], stage + 3 * TILE_BYTES + off);
            }
#pragma unroll
            for (int i = 0; i < 4; ++i) {
#pragma unroll
                for (int j = 0; j < 4; ++j) {
                    const int j2 = j >> 1, jo = j & 1;
                    mma16816(acc[i][j], ah[i], bh[j2][jo], bh[j2][2 + jo]);
                    mma16816(acc[i][j], al[i], bh[j2][jo], bh[j2][2 + jo]);
                    mma16816(acc[i][j], ah[i], bl[j2][jo], bl[j2][2 + jo]);
                }
            }
        }
        __syncthreads();
    }

    // ---- Epilogue ----
    float* Ss = (float*)smem;   // [128][132]
#pragma unroll
    for (int i = 0; i < 4; ++i) {
        const int r = wm * 64 + i * 16 + (lane >> 2);
#pragma unroll
        for (int j = 0; j < 4; ++j) {
            const int cc = wn * 32 + j * 8 + 2 * (lane & 3);
            Ss[r * 132 + cc]           = acc[i][j][0];
            Ss[r * 132 + cc + 1]       = acc[i][j][1];
            Ss[(r + 8) * 132 + cc]     = acc[i][j][2];
            Ss[(r + 8) * 132 + cc + 1] = acc[i][j][3];
        }
    }
    __syncthreads();

    const int b = m0 >> 11;
    const int nbase = m0 & (NN - 1);

    if (MODE == 0) {
#pragma unroll
        for (int it = 0; it < 16; ++it) {
            const int f = it * 256 + tid;
            const int r = f >> 5;
            const int c4 = (f & 31) << 2;
            float4 v = *(const float4*)(Ss + r * 132 + c4);
            *(float4*)(Cout + (size_t)(m0 + r) * EE + n0 + c4) = v;
        }
    } else if (MODE == 1 || (MODE == 2 && n0 < EE)) {
        const int h = (n0 & (EE - 1)) >> 7;
        __nv_bfloat16* dh = (MODE == 1 ? g_qh : g_kh) +
            ((size_t)(b * HH + h) * NN + nbase) * DD;
        __nv_bfloat16* dl = (MODE == 1 ? g_ql : g_kl) +
            ((size_t)(b * HH + h) * NN + nbase) * DD;
#pragma unroll
        for (int it = 0; it < 16; ++it) {
            const int f = it * 256 + tid;
            const int r = f >> 5;
            const int c4 = (f & 31) << 2;
            float4 v = *(const float4*)(Ss + r * 132 + c4);
            float vv[4] = {v.x, v.y, v.z, v.w};
            __nv_bfloat16 hi[4], lo[4];
#pragma unroll
            for (int q = 0; q < 4; ++q) {
                hi[q] = __float2bfloat16(vv[q]);
                lo[q] = __float2bfloat16(vv[q] - __bfloat162float(hi[q]));
            }
            *(uint2*)(dh + (size_t)r * DD + c4) = *(const uint2*)hi;
            *(uint2*)(dl + (size_t)r * DD + c4) = *(const uint2*)lo;
        }
    } else {
        // V -> g_vth/g_vtl bf16 split, transposed [B,H,D,N]
        const int h2 = (n0 - EE) >> 7;
        const int col = tid >> 1;
        const int rh2 = tid & 1;
        const size_t dof = ((size_t)(b * HH + h2) * DD + col) * NN +
                           nbase + (rh2 << 6);
        __nv_bfloat16* dsth = g_vth + dof;
        __nv_bfloat16* dstl = g_vtl + dof;
#pragma unroll
        for (int i = 0; i < 16; ++i) {
            const int r = (rh2 << 6) + (i << 2);
            __nv_bfloat16 vh4[4], vl4[4];
#pragma unroll
            for (int q = 0; q < 4; ++q) {
                const float f = Ss[(r + q) * 132 + col];
                vh4[q] = __float2bfloat16(f);
                vl4[q] = __float2bfloat16(f - __bfloat162float(vh4[q]));
            }
            *(uint2*)(dsth + (i << 2)) = *(const uint2*)vh4;
            *(uint2*)(dstl + (i << 2)) = *(const uint2*)vl4;
        }
    }
}

// ---------------------------------------------------------------------------
// Flash attention v2: mma.sync, full 3-term splits for QK^T AND PV.
// Br=128 (8 warps x 16 rows), Bc=64, D=128.
// Smem: Qh,Ql [128x272B] | 2 stages of {Kh,Kl 64x272B; Vh,Vl 128x144B}
// ---------------------------------------------------------------------------
#define FQ_BYTES 34816              // 128*272
#define FK_BYTES 17408              // 64*272
#define FV_BYTES 18432              // 128*144
#define FSTAGE (2 * FK_BYTES + 2 * FV_BYTES)        // 71680
#define FLASH2_SMEM (2 * FQ_BYTES + 2 * FSTAGE)     // 212992

__device__ __forceinline__ void load_kv(
    uint32_t stg, const __nv_bfloat16* Khg, const __nv_bfloat16* Klg,
    const __nv_bfloat16* Vhg, const __nv_bfloat16* Vlg, int j0, int tid)
{
#pragma unroll
    for (int t = 0; t < 4; ++t) {
        const int c = t * 256 + tid;        // 0..1023
        const int row = c >> 4, ch = c & 15;
        const uint32_t dst = stg + row * 272 + ch * 16;
        const size_t src = (size_t)(j0 + row) * DD + ch * 8;
        cp16(dst, Khg + src);
        cp16(dst + FK_BYTES, Klg + src);
    }
#pragma unroll
    for (int t = 0; t < 4; ++t) {
        const int c = t * 256 + tid;        // 0..1023
        const int drow = c >> 3, ch = c & 7;
        const uint32_t dst = stg + 2 * FK_BYTES + drow * 144 + ch * 16;
        const size_t src = (size_t)drow * NN + j0 + ch * 8;
        cp16(dst, Vhg + src);
        cp16(dst + FV_BYTES, Vlg + src);
    }
}

__global__ void __launch_bounds__(256, 1) flash_mma()
{
    extern __shared__ char smc[];
    const uint32_t sb = smem_u32(smc);
    const int tid = threadIdx.x;
    const int lane = tid & 31;
    const int w = tid >> 5;
    const int bh = blockIdx.y;
    const int b = bh >> 4, h = bh & (HH - 1);
    const int qt = (gridDim.x - 1) - blockIdx.x;   // long tiles first
    const int i0 = qt * 128;

    const __nv_bfloat16* Qhg = g_qh + (size_t)bh * NN * DD;
    const __nv_bfloat16* Qlg = g_ql + (size_t)bh * NN * DD;
    const __nv_bfloat16* Khg = g_kh + (size_t)bh * NN * DD;
    const __nv_bfloat16* Klg = g_kl + (size_t)bh * NN * DD;
    const __nv_bfloat16* Vhg = g_vth + (size_t)bh * DD * NN;
    const __nv_bfloat16* Vlg = g_vtl + (size_t)bh * DD * NN;

    // Q tiles (hi+lo)
#pragma unroll
    for (int t = 0; t < 8; ++t) {
        const int c = t * 256 + tid;        // 0..2047
        const int row = c >> 4, ch = c & 15;
        const uint32_t dst = sb + row * 272 + ch * 16;
        const size_t src = (size_t)(i0 + row) * DD + ch * 8;
        cp16(dst, Qhg + src);
        cp16(dst + FQ_BYTES, Qlg + src);
    }
    load_kv(sb + 2 * FQ_BYTES, Khg, Klg, Vhg, Vlg, 0, tid);
    cp_commit();

    const int nj = 2 * qt + 2;
    float m_[2] = {-1e30f, -1e30f}, l_[2] = {0.0f, 0.0f};
    float O[16][4];
#pragma unroll
    for (int nt = 0; nt < 16; ++nt)
#pragma unroll
        for (int r = 0; r < 4; ++r) O[nt][r] = 0.0f;

    const int r0 = w * 16 + (lane >> 2);

    for (int jt = 0; jt < nj; ++jt) {
        const uint32_t stg = sb + 2 * FQ_BYTES + (jt & 1) * FSTAGE;
        if (jt + 1 < nj) {
            load_kv(sb + 2 * FQ_BYTES + ((jt + 1) & 1) * FSTAGE,
                    Khg, Klg, Vhg, Vlg, (jt + 1) * 64, tid);
            cp_commit();
            asm volatile("cp.async.wait_group 1;");
        } else {
            asm volatile("cp.async.wait_group 0;");
        }
        __syncthreads();

        // ---- S = Q K^T (3-term split) ----
        float S[8][4];
#pragma unroll
        for (int nt = 0; nt < 8; ++nt)
#pragma unroll
            for (int r = 0; r < 4; ++r) S[nt][r] = 0.0f;

        const int lrA = w * 16 + ((lane >> 3) & 1) * 8 + (lane & 7);
        const int cA16 = (lane >> 4) & 1;
        const int lrB = ((lane >> 4) & 1) * 8 + (lane & 7);
        const int cB16 = (lane >> 3) & 1;

#pragma unroll
        for (int ks = 0; ks < 8; ++ks) {
            uint32_t ah[4], al[4];
            const uint32_t qoff = lrA * 272 + ks * 32 + cA16 * 16;
            ldmx4(ah, sb + qoff);
            ldmx4(al, sb + FQ_BYTES + qoff);
#pragma unroll
            for (int jn2 = 0; jn2 < 4; ++jn2) {
                uint32_t bhf[4], blf[4];
                const uint32_t koff = (jn2 * 16 + lrB) * 272 + ks * 32 + cB16 * 16;
                ldmx4(bhf, stg + koff);
                ldmx4(blf, stg + FK_BYTES + koff);
                mma16816(S[2 * jn2],     ah, bhf[0], bhf[1]);
                mma16816(S[2 * jn2],     al, bhf[0], bhf[1]);
                mma16816(S[2 * jn2],     ah, blf[0], blf[1]);
                mma16816(S[2 * jn2 + 1], ah, bhf[2], bhf[3]);
                mma16816(S[2 * jn2 + 1], al, bhf[2], bhf[3]);
                mma16816(S[2 * jn2 + 1], ah, blf[2], blf[3]);
            }
        }

        // ---- scale + causal mask ----
        const int j0 = jt * 64;
#pragma unroll
        for (int nt = 0; nt < 8; ++nt)
#pragma unroll
            for (int r = 0; r < 4; ++r) S[nt][r] *= SCALE;

        if (jt >= nj - 2) {
#pragma unroll
            for (int nt = 0; nt < 8; ++nt) {
                const int jc = j0 + nt * 8 + (lane & 3) * 2;
#pragma unroll
                for (int r = 0; r < 4; ++r) {
                    const int i = i0 + r0 + (r >> 1) * 8;
                    if (jc + (r & 1) > i) S[nt][r] = -1e30f;
                }
            }
        }

        // ---- online softmax (rows: r0, r0+8) ----
        float rm0 = -1e30f, rm1 = -1e30f;
#pragma unroll
        for (int nt = 0; nt < 8; ++nt) {
            rm0 = fmaxf(rm0, fmaxf(S[nt][0], S[nt][1]));
            rm1 = fmaxf(rm1, fmaxf(S[nt][2], S[nt][3]));
        }
        rm0 = fmaxf(rm0, __shfl_xor_sync(0xffffffffu, rm0, 1));
        rm0 = fmaxf(rm0, __shfl_xor_sync(0xffffffffu, rm0, 2));
        rm1 = fmaxf(rm1, __shfl_xor_sync(0xffffffffu, rm1, 1));
        rm1 = fmaxf(rm1, __shfl_xor_sync(0xffffffffu, rm1, 2));

        const float mn0 = fmaxf(m_[0], rm0);
        const float mn1 = fmaxf(m_[1], rm1);
        const float al0 = __expf(m_[0] - mn0);
        const float al1 = __expf(m_[1] - mn1);
        float rs0 = 0.0f, rs1 = 0.0f;
#pragma unroll
        for (int nt = 0; nt < 8; ++nt) {
            S[nt][0] = __expf(S[nt][0] - mn0);
            S[nt][1] = __expf(S[nt][1] - mn0);
            S[nt][2] = __expf(S[nt][2] - mn1);
            S[nt][3] = __expf(S[nt][3] - mn1);
            rs0 += S[nt][0] + S[nt][1];
            rs1 += S[nt][2] + S[nt][3];
        }
        rs0 += __shfl_xor_sync(0xffffffffu, rs0, 1);
        rs0 += __shfl_xor_sync(0xffffffffu, rs0, 2);
        rs1 += __shfl_xor_sync(0xffffffffu, rs1, 1);
        rs1 += __shfl_xor_sync(0xffffffffu, rs1, 2);

        l_[0] = l_[0] * al0 + rs0;
        l_[1] = l_[1] * al1 + rs1;
        m_[0] = mn0; m_[1] = mn1;

#pragma unroll
        for (int nt = 0; nt < 16; ++nt) {
            O[nt][0] *= al0; O[nt][1] *= al0;
            O[nt][2] *= al1; O[nt][3] *= al1;
        }

        // ---- O += P V  (3-term split: Ph*Vh + Pl*Vh + Ph*Vl) ----
#pragma unroll
        for (int kc = 0; kc < 4; ++kc) {
            // Split P fragments: hi + lo
            float p00 = S[2 * kc][0],     p01 = S[2 * kc][1];
            float p02 = S[2 * kc][2],     p03 = S[2 * kc][3];
            float p10 = S[2 * kc + 1][0], p11 = S[2 * kc + 1][1];
            float p12 = S[2 * kc + 1][2], p13 = S[2 * kc + 1][3];
            uint32_t pah[4], pal[4];
            pah[0] = packbf(p00, p01);
            pah[1] = packbf(p02, p03);
            pah[2] = packbf(p10, p11);
            pah[3] = packbf(p12, p13);
            {
                __nv_bfloat162 t0 = *(__nv_bfloat162*)&pah[0];
                __nv_bfloat162 t1 = *(__nv_bfloat162*)&pah[1];
                __nv_bfloat162 t2 = *(__nv_bfloat162*)&pah[2];
                __nv_bfloat162 t3 = *(__nv_bfloat162*)&pah[3];
                pal[0] = packbf(p00 - __bfloat162float(t0.x), p01 - __bfloat162float(t0.y));
                pal[1] = packbf(p02 - __bfloat162float(t1.x), p03 - __bfloat162float(t1.y));
                pal[2] = packbf(p10 - __bfloat162float(t2.x), p11 - __bfloat162float(t2.y));
                pal[3] = packbf(p12 - __bfloat162float(t3.x), p13 - __bfloat162float(t3.y));
            }
#pragma unroll
            for (int dt2 = 0; dt2 < 8; ++dt2) {
                uint32_t vbh[4], vbl[4];
                const uint32_t voff = 2 * FK_BYTES +
                    (dt2 * 16 + lrB) * 144 + kc * 32 + cB16 * 16;
                ldmx4(vbh, stg + voff);
                ldmx4(vbl, stg + FV_BYTES + voff);
                mma16816(O[2 * dt2],     pah, vbh[0], vbh[1]);
                mma16816(O[2 * dt2],     pal, vbh[0], vbh[1]);
                mma16816(O[2 * dt2],     pah, vbl[0], vbl[1]);
                mma16816(O[2 * dt2 + 1], pah, vbh[2], vbh[3]);
                mma16816(O[2 * dt2 + 1], pal, vbh[2], vbh[3]);
                mma16816(O[2 * dt2 + 1], pah, vbl[2], vbl[3]);
            }
        }
        __syncthreads();
    }

    // ---- epilogue: normalize, split-bf16 store to s_ah/s_al [B,N,E] ----
#pragma unroll
    for (int rh = 0; rh < 2; ++rh) {
        const int i = i0 + r0 + rh * 8;
        const float inv = 1.0f / l_[rh];
#pragma unroll
        for (int nt = 0; nt < 16; ++nt) {
            const int d = nt * 8 + (lane & 3) * 2;
            const size_t idx = ((size_t)(b * NN + i)) * EE + h * DD + d;
            const float o0 = O[nt][2 * rh] * inv;
            const float o1 = O[nt][2 * rh + 1] * inv;
            const __nv_bfloat16 h0 = __float2bfloat16(o0);
            const __nv_bfloat16 h1 = __float2bfloat16(o1);
            const float l0f = o0 - __bfloat162float(h0);
            const float l1f = o1 - __bfloat162float(h1);
            __nv_bfloat16 hp[2] = {h0, h1};
            __nv_bfloat16 lp[2] = {__float2bfloat16(l0f), __float2bfloat16(l1f)};
            *(uint32_t*)(s_ah + idx) = *(const uint32_t*)hp;
            *(uint32_t*)(s_al + idx) = *(const uint32_t*)lp;
        }
    }
}

// ---------------------------------------------------------------------------
// Launch
// ---------------------------------------------------------------------------
extern "C" void kernel_launch(void* const* d_in, const int* in_sizes, int n_in,
                              void* d_out, int out_size)
{
    const float* x    = (const float*)d_in[0];
    const float* Wq   = (const float*)d_in[1];
    const float* Wkv  = (const float*)d_in[2];
    const float* Wout = (const float*)d_in[3];
    float* out = (float*)d_out;

    void *xh, *xl, *wqh, *wql, *wkh, *wkl, *woh, *wol, *ah, *al;
    cudaGetSymbolAddress(&xh, s_xh);   cudaGetSymbolAddress(&xl, s_xl);
    cudaGetSymbolAddress(&wqh, s_wqh); cudaGetSymbolAddress(&wql, s_wql);
    cudaGetSymbolAddress(&wkh, s_wkh); cudaGetSymbolAddress(&wkl, s_wkl);
    cudaGetSymbolAddress(&woh, s_woh); cudaGetSymbolAddress(&wol, s_wol);
    cudaGetSymbolAddress(&ah, s_ah);   cudaGetSymbolAddress(&al, s_al);

    split_kernel<<<8192, 256>>>(x,    (__nv_bfloat16*)xh,  (__nv_bfloat16*)xl,  2097152);
    split_kernel<<<4096, 256>>>(Wq,   (__nv_bfloat16*)wqh, (__nv_bfloat16*)wql, 1048576);
    split_kernel<<<8192, 256>>>(Wkv,  (__nv_bfloat16*)wkh, (__nv_bfloat16*)wkl, 2097152);
    split_kernel<<<4096, 256>>>(Wout, (__nv_bfloat16*)woh, (__nv_bfloat16*)wol, 1048576);

    cudaFuncSetAttribute(gemm_mma<0>, cudaFuncAttributeMaxDynamicSharedMemorySize, GEMM_SMEM);
    cudaFuncSetAttribute(gemm_mma<1>, cudaFuncAttributeMaxDynamicSharedMemorySize, GEMM_SMEM);
    cudaFuncSetAttribute(gemm_mma<2>, cudaFuncAttributeMaxDynamicSharedMemorySize, GEMM_SMEM);

    gemm_mma<1><<<dim3(EE / 128, MTOT / 128), 256, GEMM_SMEM>>>(
        (const __nv_bfloat16*)xh, (const __nv_bfloat16*)xl,
        (const __nv_bfloat16*)wqh, (const __nv_bfloat16*)wql, nullptr, EE);
    gemm_mma<2><<<dim3(2 * EE / 128, MTOT / 128), 256, GEMM_SMEM>>>(
        (const __nv_bfloat16*)xh, (const __nv_bfloat16*)xl,
        (const __nv_bfloat16*)wkh, (const __nv_bfloat16*)wkl, nullptr, EE);

    cudaFuncSetAttribute(flash_mma, cudaFuncAttributeMaxDynamicSharedMemorySize,
                         FLASH2_SMEM);
    flash_mma<<<dim3(NN / 128, BB * HH), 256, FLASH2_SMEM>>>();

    gemm_mma<0><<<dim3(EE / 128, MTOT / 128), 256, GEMM_SMEM>>>(
        (const __nv_bfloat16*)ah, (const __nv_bfloat16*)al,
        (const __nv_bfloat16*)woh, (const __nv_bfloat16*)wol, out, EE);
}